// round 3
// baseline (speedup 1.0000x reference)
#include <cuda_runtime.h>

// AttnDecoder single decode step, fully fused persistent kernel.
// Live dataflow only (attention branch in the reference is dead code):
//   e = emb[tok]
//   gates = W_ih@e + b_ih + W_hh@h0 + b_hh ; LSTM cell -> h_new, c_new
//   logits = out_W @ h_new + out_b ; log_softmax
// Output layout (float32, out_size = V + 2H):
//   [0, V)  log_probs   [V, V+H) h_new   [V+H, V+2H) c_new

#define H 1024
#define V 50000
#define NBLK 148
#define NTHR 1024
#define NWARPS_BLK (NTHR / 32)          // 32
#define NWARP_TOT (NBLK * NWARPS_BLK)   // 4736
#define RPW 4                           // vocab rows per warp per iteration

// Scratch (__device__ globals; no allocations allowed)
__device__ float g_gates[4 * H];
__device__ float g_pm[NBLK];
__device__ float g_ps[NBLK];
__device__ unsigned g_cnt[2];
__device__ unsigned g_gen[2];

// Sense-reversing grid barrier. All NBLK blocks are co-resident (1/SM).
__device__ __forceinline__ void gridbar(int id)
{
    __threadfence();          // publish this thread's prior writes
    __syncthreads();
    if (threadIdx.x == 0) {
        volatile unsigned* genp = &g_gen[id];
        const unsigned gen = *genp;              // read gen BEFORE arriving
        const unsigned t = atomicAdd(&g_cnt[id], 1u);
        if (t == NBLK - 1) {
            g_cnt[id] = 0;
            __threadfence();
            atomicAdd(&g_gen[id], 1u);           // release
        } else {
            while (*genp == gen) __nanosleep(64);
        }
    }
    __syncthreads();
    __threadfence();          // acquire side
}

// Streaming log-sum-exp merge of (m1,s1) <- (m1,s1)+(m2,s2)
__device__ __forceinline__ void lse_merge(float& m1, float& s1, float m2, float s2)
{
    const float M = fmaxf(m1, m2);
    s1 = s1 * expf(m1 - M) + s2 * expf(m2 - M);
    m1 = M;
}

__global__ void __launch_bounds__(NTHR, 1) k_fused(
    const long long* __restrict__ tok_p,
    const float* __restrict__ emb,
    const float* __restrict__ h0,
    const float* __restrict__ c0,
    const float* __restrict__ W_ih,
    const float* __restrict__ W_hh,
    const float* __restrict__ b_ih,
    const float* __restrict__ b_hh,
    const float* __restrict__ out_W,
    const float* __restrict__ out_b,
    float* __restrict__ out)
{
    __shared__ float se[H];       // embedded token
    __shared__ float sh[H];       // h0, later reused as h_new
    __shared__ float sm_m[NWARPS_BLK];
    __shared__ float sm_s[NWARPS_BLK];
    __shared__ float s_logZ;

    const int tid  = threadIdx.x;
    const int lane = tid & 31;
    const int wid  = tid >> 5;
    const int gwarp = blockIdx.x * NWARPS_BLK + wid;

    // ---- Phase 0: stage e and h0 in this block's smem --------------------
    {
        const long long tok = *tok_p;
        const float* erow = emb + tok * (long long)H;
        for (int t = tid; t < H; t += NTHR) {
            se[t] = erow[t];
            sh[t] = h0[t];
        }
    }
    __syncthreads();

    // ---- Phase 1: gate rows. One warp per row of the 4H x H matvec pair --
    if (gwarp < 4 * H) {
        const int row = gwarp;
        const float4* wi = (const float4*)(W_ih + (long long)row * H);
        const float4* wh = (const float4*)(W_hh + (long long)row * H);
        const float4* e4 = (const float4*)se;
        const float4* h4 = (const float4*)sh;
        float s = 0.f;
#pragma unroll
        for (int k = 0; k < H / 128; k++) {
            const int t = lane + k * 32;
            float4 a = wi[t], b = e4[t];
            s += a.x * b.x + a.y * b.y + a.z * b.z + a.w * b.w;
            float4 c = wh[t], d = h4[t];
            s += c.x * d.x + c.y * d.y + c.z * d.z + c.w * d.w;
        }
#pragma unroll
        for (int o = 16; o; o >>= 1) s += __shfl_xor_sync(0xFFFFFFFFu, s, o);
        if (lane == 0) g_gates[row] = s + b_ih[row] + b_hh[row];
    }

    gridbar(0);   // all gate pre-activations visible

    // ---- Phase 1b: LSTM elementwise; every block builds h_new in its smem
    for (int j = tid; j < H; j += NTHR) {
        const float gi = g_gates[j];
        const float gf = g_gates[H + j];
        const float gg = g_gates[2 * H + j];
        const float go = g_gates[3 * H + j];
        const float i_ = 1.f / (1.f + expf(-gi));
        const float f_ = 1.f / (1.f + expf(-gf));
        const float o_ = 1.f / (1.f + expf(-go));
        const float g_ = tanhf(gg);
        const float c_new = f_ * c0[j] + i_ * g_;
        const float h_new = o_ * tanhf(c_new);
        sh[j] = h_new;                       // reuse sh as h_new
        if (blockIdx.x == 0) {
            out[V + j]     = h_new;
            out[V + H + j] = c_new;
        }
    }
    __syncthreads();

    // ---- Phase 2: logits matvec, RPW rows per warp per iteration --------
    // 4x the in-flight loads per warp; reduction + LSE tail amortized 4x.
    float m_w = -1e30f, s_w = 0.f;
    {
        const float4* h4 = (const float4*)sh;
        for (int row0 = gwarp * RPW; row0 < V; row0 += NWARP_TOT * RPW) {
            const float4* w0 = (const float4*)(out_W + (long long)(row0 + 0) * H);
            const float4* w1 = (const float4*)(out_W + (long long)(row0 + 1) * H);
            const float4* w2 = (const float4*)(out_W + (long long)(row0 + 2) * H);
            const float4* w3 = (const float4*)(out_W + (long long)(row0 + 3) * H);
            float a0 = 0.f, a1 = 0.f, a2 = 0.f, a3 = 0.f;
#pragma unroll
            for (int k = 0; k < H / 128; k++) {
                const int t = lane + k * 32;
                const float4 b = h4[t];
                float4 v;
                v = w0[t]; a0 += v.x * b.x + v.y * b.y + v.z * b.z + v.w * b.w;
                v = w1[t]; a1 += v.x * b.x + v.y * b.y + v.z * b.z + v.w * b.w;
                v = w2[t]; a2 += v.x * b.x + v.y * b.y + v.z * b.z + v.w * b.w;
                v = w3[t]; a3 += v.x * b.x + v.y * b.y + v.z * b.z + v.w * b.w;
            }
#pragma unroll
            for (int o = 16; o; o >>= 1) {
                a0 += __shfl_xor_sync(0xFFFFFFFFu, a0, o);
                a1 += __shfl_xor_sync(0xFFFFFFFFu, a1, o);
                a2 += __shfl_xor_sync(0xFFFFFFFFu, a2, o);
                a3 += __shfl_xor_sync(0xFFFFFFFFu, a3, o);
            }
            // V % RPW == 0, so row0+3 < V always holds here.
            const float x0 = a0 + out_b[row0 + 0];
            const float x1 = a1 + out_b[row0 + 1];
            const float x2 = a2 + out_b[row0 + 2];
            const float x3 = a3 + out_b[row0 + 3];
            if (lane == 0) {
                float4 o4 = make_float4(x0, x1, x2, x3);
                *(float4*)(out + row0) = o4;        // out+row0 is 16B-aligned
            }
            // one streaming-LSE update for 4 rows (identical in all lanes)
            const float m4 = fmaxf(fmaxf(x0, x1), fmaxf(x2, x3));
            const float s4 = expf(x0 - m4) + expf(x1 - m4)
                           + expf(x2 - m4) + expf(x3 - m4);
            lse_merge(m_w, s_w, m4, s4);
        }
    }
    if (lane == 0) { sm_m[wid] = m_w; sm_s[wid] = s_w; }
    __syncthreads();
    if (wid == 0) {
        float m = sm_m[lane], s = sm_s[lane];
#pragma unroll
        for (int o = 16; o; o >>= 1) {
            const float m2 = __shfl_xor_sync(0xFFFFFFFFu, m, o);
            const float s2 = __shfl_xor_sync(0xFFFFFFFFu, s, o);
            lse_merge(m, s, m2, s2);
        }
        if (lane == 0) { g_pm[blockIdx.x] = m; g_ps[blockIdx.x] = s; }
    }

    gridbar(1);   // all logits + partials visible

    // ---- Phase 3: combine 148 partials (warp 0, fixed order), subtract --
    if (wid == 0) {
        float m = -1e30f, s = 0.f;
        for (int b = lane; b < NBLK; b += 32)
            lse_merge(m, s, g_pm[b], g_ps[b]);
#pragma unroll
        for (int o = 16; o; o >>= 1) {
            const float m2 = __shfl_xor_sync(0xFFFFFFFFu, m, o);
            const float s2 = __shfl_xor_sync(0xFFFFFFFFu, s, o);
            lse_merge(m, s, m2, s2);
        }
        if (lane == 0) s_logZ = m + logf(s);
    }
    __syncthreads();
    const float logZ = s_logZ;
    for (int i = blockIdx.x * NTHR + tid; i < V; i += NBLK * NTHR)
        out[i] -= logZ;
}

extern "C" void kernel_launch(void* const* d_in, const int* in_sizes, int n_in,
                              void* d_out, int out_size)
{
    (void)in_sizes; (void)n_in; (void)out_size;
    const long long* tok  = (const long long*)d_in[0];
    const float* h0   = (const float*)d_in[1];
    const float* c0   = (const float*)d_in[2];
    // d_in[3] encoder_outputs, d_in[5..8] attn/comb params: dead code, skipped
    const float* emb  = (const float*)d_in[4];
    const float* W_ih = (const float*)d_in[9];
    const float* W_hh = (const float*)d_in[10];
    const float* b_ih = (const float*)d_in[11];
    const float* b_hh = (const float*)d_in[12];
    const float* outW = (const float*)d_in[13];
    const float* outb = (const float*)d_in[14];
    float* out = (float*)d_out;

    k_fused<<<NBLK, NTHR>>>(tok, emb, h0, c0, W_ih, W_hh, b_ih, b_hh,
                            outW, outb, out);
}